// round 17
// baseline (speedup 1.0000x reference)
#include <cuda_runtime.h>
#include <cuda_fp16.h>
#include <math.h>
#include <stdint.h>

typedef unsigned long long ull;

#define NB 64
#define NH 256
#define NG 768
#define NP 32
#define TSEQ 64
#define TDEC 54

// -------- device-global scratch --------
__device__ float g_z[NB * NH];
__device__ float g_henc[NB * NH];
__device__ float g_WtEnc[256 * 768];      // W_hh_enc^T [k][j]
__device__ float g_mwT[NH * NH];
__device__ float g_swT[NH * NH];
__device__ __half g_Wfrag[32 * 196608];   // [p][slice 8][24576 halfs] fp16 W_hh_dec frag-order
__device__ __half g_WihFrag[32 * 24576];  // [p][24576 halfs] fp16 W_ih_dec frag-order (K=32)

// -------- f32x2 helpers --------
__device__ __forceinline__ ull pk(float x, float y) {
    ull r; asm("mov.b64 %0, {%1,%2};" : "=l"(r) : "f"(x), "f"(y)); return r;
}
__device__ __forceinline__ ull pk2(float x) { return pk(x, x); }
__device__ __forceinline__ void upk(ull v, float& x, float& y) {
    asm("mov.b64 {%0,%1}, %2;" : "=f"(x), "=f"(y) : "l"(v));
}
#define FMA2(acc, a, b) asm("fma.rn.f32x2 %0, %1, %2, %0;" : "+l"(acc) : "l"(a), "l"(b))
__device__ __forceinline__ float sigm(float x) { return 1.0f / (1.0f + expf(-x)); }

// -------- mbarrier / bulk-copy helpers --------
__device__ __forceinline__ uint32_t smem_u32(const void* p) {
    uint32_t a;
    asm("{ .reg .u64 t; cvta.to.shared.u64 t, %1; cvt.u32.u64 %0, t; }" : "=r"(a) : "l"(p));
    return a;
}
__device__ __forceinline__ void mbar_init(uint32_t m, uint32_t c) {
    asm volatile("mbarrier.init.shared.b64 [%0], %1;" :: "r"(m), "r"(c) : "memory");
}
__device__ __forceinline__ void mbar_expect(uint32_t m, uint32_t b) {
    asm volatile("mbarrier.arrive.expect_tx.shared.b64 _, [%0], %1;" :: "r"(m), "r"(b) : "memory");
}
__device__ __forceinline__ void bulk_cp(uint32_t dst, const void* src, uint32_t bytes, uint32_t m) {
    asm volatile("cp.async.bulk.shared::cluster.global.mbarrier::complete_tx::bytes [%0], [%1], %2, [%3];"
        :: "r"(dst), "l"(src), "r"(bytes), "r"(m) : "memory");
}
__device__ __forceinline__ void mbar_wait(uint32_t m, uint32_t ph) {
    asm volatile(
        "{\n\t.reg .pred P1;\n\tW%=:\n\t"
        "mbarrier.try_wait.parity.acquire.cta.shared::cta.b64 P1, [%0], %1, 0x989680;\n\t"
        "@P1 bra.uni D%=;\n\tbra.uni W%=;\n\tD%=:\n\t}" :: "r"(m), "r"(ph) : "memory");
}

// -------- HMMA m16n8k16 fp16 -> fp32 --------
__device__ __forceinline__ void hmma(float* c, const uint4& a, uint32_t b0, uint32_t b1) {
    asm("mma.sync.aligned.m16n8k16.row.col.f32.f16.f16.f32 "
        "{%0,%1,%2,%3}, {%4,%5,%6,%7}, {%8,%9}, {%0,%1,%2,%3};"
        : "+f"(c[0]), "+f"(c[1]), "+f"(c[2]), "+f"(c[3])
        : "r"(a.x), "r"(a.y), "r"(a.z), "r"(a.w), "r"(b0), "r"(b1));
}
__device__ __forceinline__ uint32_t h2pack(float a, float b) {
    __half2 v = __floats2half2_rn(a, b);
    return *reinterpret_cast<uint32_t*>(&v);
}

// ======================= W_hh_dec -> fp16 fragment-order pack =======================
__global__ void wprep_kernel(const float* __restrict__ W) {
    int p = blockIdx.y;
    int i = blockIdx.x * 256 + threadIdx.x;   // 0..24575
    int mt = i >> 9, kt = (i >> 5) & 15, lane = i & 31;
    int row = mt * 16 + (lane >> 2);
    int k0 = kt * 16 + ((lane & 3) << 1);
    const float* Wp = W + (size_t)p * NG * NH;
    float2 v0 = *reinterpret_cast<const float2*>(Wp + (size_t)row * NH + k0);
    float2 v1 = *reinterpret_cast<const float2*>(Wp + (size_t)(row + 8) * NH + k0);
    float2 v2 = *reinterpret_cast<const float2*>(Wp + (size_t)row * NH + k0 + 8);
    float2 v3 = *reinterpret_cast<const float2*>(Wp + (size_t)(row + 8) * NH + k0 + 8);
    uint4 o = make_uint4(h2pack(v0.x, v0.y), h2pack(v1.x, v1.y),
                         h2pack(v2.x, v2.y), h2pack(v3.x, v3.y));
    size_t dst = (size_t)p * 196608 + (size_t)(kt >> 1) * 24576
               + (size_t)((mt * 2 + (kt & 1)) * 32 + lane) * 8;
    *reinterpret_cast<uint4*>(g_Wfrag + dst) = o;
}

// ======================= W_ih_dec -> fp16 fragment-order pack (K=32) =======================
__global__ void wprep_ih_kernel(const float* __restrict__ W) {
    int p = blockIdx.y;
    int i = blockIdx.x * 256 + threadIdx.x;   // 0..3071
    int mt = i >> 6, kt = (i >> 5) & 1, lane = i & 31;
    int row = mt * 16 + (lane >> 2);
    int k0 = kt * 16 + ((lane & 3) << 1);
    const float* Wp = W + (size_t)p * NG * NP;
    float2 v0 = *reinterpret_cast<const float2*>(Wp + (size_t)row * NP + k0);
    float2 v1 = *reinterpret_cast<const float2*>(Wp + (size_t)(row + 8) * NP + k0);
    float2 v2 = *reinterpret_cast<const float2*>(Wp + (size_t)row * NP + k0 + 8);
    float2 v3 = *reinterpret_cast<const float2*>(Wp + (size_t)(row + 8) * NP + k0 + 8);
    uint4 o = make_uint4(h2pack(v0.x, v0.y), h2pack(v1.x, v1.y),
                         h2pack(v2.x, v2.y), h2pack(v3.x, v3.y));
    size_t dst = (size_t)p * 24576 + (size_t)((mt * 2 + kt) * 32 + lane) * 8;
    *reinterpret_cast<uint4*>(g_WihFrag + dst) = o;
}

// ======================= W_hh_enc transpose =======================
__global__ void tr_enc_kernel(const float* __restrict__ W) {
    __shared__ float tile[32][33];
    int k0 = blockIdx.x * 32, j0 = blockIdx.y * 32;
    int x = threadIdx.x, y0 = threadIdx.y;
#pragma unroll
    for (int dy = 0; dy < 32; dy += 8) tile[y0 + dy][x] = W[(j0 + y0 + dy) * NH + k0 + x];
    __syncthreads();
#pragma unroll
    for (int dy = 0; dy < 32; dy += 8) g_WtEnc[(k0 + y0 + dy) * NG + j0 + x] = tile[x][y0 + dy];
}

// ======================= fc weight transpose (x2) =======================
__global__ void trf_kernel(const float* __restrict__ mw, const float* __restrict__ sw_) {
    __shared__ float tile[32][33];
    int sel = blockIdx.z;
    const float* Wp = sel ? sw_ : mw;
    float* Wtp = sel ? g_swT : g_mwT;
    int k0 = blockIdx.x * 32, j0 = blockIdx.y * 32;
    int x = threadIdx.x, y0 = threadIdx.y;
#pragma unroll
    for (int dy = 0; dy < 32; dy += 8) tile[y0 + dy][x] = Wp[(j0 + y0 + dy) * NH + k0 + x];
    __syncthreads();
#pragma unroll
    for (int dy = 0; dy < 32; dy += 8) Wtp[(k0 + y0 + dy) * NH + j0 + x] = tile[x][y0 + dy];
}

// ======================= encoder GRU (TMA-streamed fp32, unchanged) =======================
#define ENC_SF (16 * 768)
#define ENC_SB (ENC_SF * 4)
__global__ void __launch_bounds__(512, 1)
enc_kernel(const float* __restrict__ X, const float* __restrict__ Wih,
           const float* __restrict__ bih, const float* __restrict__ bhh) {
    extern __shared__ __align__(1024) float sm[];
    float* sW = sm;           float* sWih = sm + 24576;
    float* sh = sm + 49920;   float* sbih = sm + 50944;
    float* sbhh = sm + 51712; float* sx = sm + 52480;
    float* smb = sm + 52736;
    int tid = threadIdx.x, half = tid >> 8, tl = tid & 255;
    int b0 = blockIdx.x * 4;
    uint32_t mb0 = smem_u32(smb), mb1 = mb0 + 8, sWa = smem_u32(sW);
#pragma unroll
    for (int s = 0; s < 12; s++) {
        int fidx = tid + 512 * s;
        int j = fidx >> 3, iq = fidx & 7;
        float4 v = *reinterpret_cast<const float4*>(Wih + j * 32 + iq * 4);
        float* d = sWih + j * 33 + iq * 4;
        d[0] = v.x; d[1] = v.y; d[2] = v.z; d[3] = v.w;
    }
    for (int i = tid; i < 768; i += 512) { sbih[i] = bih[i]; sbhh[i] = bhh[i]; }
    for (int i = tid; i < 1024; i += 512) sh[i] = 0.0f;
    if (tid < 128) { int b = tid >> 5, i = tid & 31; sx[i * 4 + b] = X[((b0 + b) * TSEQ) * NP + i]; }
    if (tid == 0) { mbar_init(mb0, 1); mbar_init(mb1, 1); }
    __syncthreads();
    if (tid == 0) {
        mbar_expect(mb0, ENC_SB); bulk_cp(sWa, g_WtEnc, ENC_SB, mb0);
        mbar_expect(mb1, ENC_SB); bulk_cp(sWa + ENC_SB, g_WtEnc + ENC_SF, ENC_SB, mb1);
    }
    int ph0 = 0, ph1 = 0, sl = 0;
    const int NSL = 160;
    float bi0 = sbih[tl], bi1 = sbih[tl + 256], bi2 = sbih[tl + 512];
    float bh0 = sbhh[tl], bh1 = sbhh[tl + 256], bh2 = sbhh[tl + 512];
    for (int t = 0; t < 10; t++) {
        ull a0 = pk2(bi0 + bh0), a1 = pk2(bi1 + bh1), a2 = pk2(bh2), g2 = pk2(bi2);
        const float* sxc = sx + (t & 1) * 128;
        const float* w0p = sWih + tl * 33;
        const float* w1p = sWih + (tl + 256) * 33;
        const float* w2p = sWih + (tl + 512) * 33;
#pragma unroll
        for (int i = 0; i < 32; i++) {
            ull x2 = *reinterpret_cast<const ull*>(sxc + i * 4 + half * 2);
            FMA2(a0, pk2(w0p[i]), x2); FMA2(a1, pk2(w1p[i]), x2); FMA2(g2, pk2(w2p[i]), x2);
        }
        if (t < 9 && tid < 128) {
            int b = tid >> 5, i = tid & 31;
            sx[((t + 1) & 1) * 128 + i * 4 + b] = X[((b0 + b) * TSEQ + t + 1) * NP + i];
        }
        for (int ks = 0; ks < 16; ks++) {
            int cur = sl & 1;
            if (cur == 0) { mbar_wait(mb0, ph0); ph0 ^= 1; } else { mbar_wait(mb1, ph1); ph1 ^= 1; }
            const float* base = sW + cur * ENC_SF;
#pragma unroll
            for (int kl = 0; kl < 16; kl++) {
                const float* wr = base + kl * 768;
                ull w0 = pk2(wr[tl]), w1 = pk2(wr[tl + 256]), w2 = pk2(wr[tl + 512]);
                ull h2 = *reinterpret_cast<const ull*>(sh + (ks * 16 + kl) * 4 + half * 2);
                FMA2(a0, w0, h2); FMA2(a1, w1, h2); FMA2(a2, w2, h2);
            }
            __syncthreads();
            if (tid == 0 && sl + 2 < NSL) {
                uint32_t mb = cur ? mb1 : mb0;
                mbar_expect(mb, ENC_SB);
                bulk_cp(sWa + cur * ENC_SB, g_WtEnc + (size_t)((sl + 2) & 15) * ENC_SF, ENC_SB, mb);
            }
            sl++;
        }
        float a0x, a0y, a1x, a1y, a2x, a2y, g2x, g2y;
        upk(a0, a0x, a0y); upk(a1, a1x, a1y); upk(a2, a2x, a2y); upk(g2, g2x, g2y);
        int bs = half * 2;
        { float r = sigm(a0x), z = sigm(a1x); float n = tanhf(g2x + r * a2x);
          sh[tl * 4 + bs] = (1.0f - z) * n + z * sh[tl * 4 + bs]; }
        { float r = sigm(a0y), z = sigm(a1y); float n = tanhf(g2y + r * a2y);
          sh[tl * 4 + bs + 1] = (1.0f - z) * n + z * sh[tl * 4 + bs + 1]; }
        __syncthreads();
    }
    g_henc[(b0 + half * 2 + 0) * NH + tl] = sh[tl * 4 + half * 2 + 0];
    g_henc[(b0 + half * 2 + 1) * NH + tl] = sh[tl * 4 + half * 2 + 1];
}

// ======================= latent =======================
__global__ void __launch_bounds__(256)
lat_kernel(const float* __restrict__ eps, const float* __restrict__ mb,
           const float* __restrict__ sb_, float* __restrict__ out) {
    __shared__ float hh[NH];
    int b = blockIdx.x, tid = threadIdx.x;
    hh[tid] = g_henc[b * NH + tid];
    __syncthreads();
    float am = mb[tid], as = sb_[tid];
    const float* mT = g_mwT + tid;
    const float* sT = g_swT + tid;
#pragma unroll 8
    for (int k = 0; k < NH; k++) { float h = hh[k]; am += mT[k * NH] * h; as += sT[k * NH] * h; }
    out[126976 + b * NH + tid] = am;
    out[110592 + b * NH + tid] = as;
    g_z[b * NH + tid] = am + expf(0.5f * as) * eps[b * NH + tid];
}

// ======================= decoder GRU: mma.sync fp16, 64 CTAs x 512 thr, b=32/CTA =============
// SMEM layout (bytes):
//   0        .. 147456  : 3 x 48KB W chunk slots (TMA)
//   147456   .. 164352  : shi [32 b][264] fp16
//   164352   .. 181248  : slo [32 b][264] fp16
//   181248   .. 185856  : sx  [2][32 b][36] fp16 (dec_in step double-buffer)
//   185856   .. 188928  : sbhh [768] f32
//   188928   .. 192000  : sbih [768] f32
//   192000   .. 193024  : slw [256] f32
//   193024   .. 193280  : sout [2][32] f32
//   193280   .. 193304  : mbarriers x3
#define SLOT_B   49152
#define OFF_SHI  147456
#define OFF_SLO  164352
#define OFF_SX   181248
#define OFF_BHH  185856
#define OFF_BIH  188928
#define OFF_LW   192000
#define OFF_SOUT 193024
#define OFF_MB   193280
#define DEC_SMEM 193408

__global__ void __launch_bounds__(512, 1)
dec_mma_kernel(const float* __restrict__ X,
               const float* __restrict__ bih_all, const float* __restrict__ bhh_all,
               const float* __restrict__ lw_all, const float* __restrict__ lb_all,
               float* __restrict__ out) {
    extern __shared__ __align__(128) char smc[];
    __half* shi = (__half*)(smc + OFF_SHI);
    __half* slo = (__half*)(smc + OFF_SLO);
    __half* sx  = (__half*)(smc + OFF_SX);
    float* sbhh = (float*)(smc + OFF_BHH);
    float* sbih = (float*)(smc + OFF_BIH);
    float* slw  = (float*)(smc + OFF_LW);
    float* sout = (float*)(smc + OFF_SOUT);
    int tid = threadIdx.x, lane = tid & 31, w = tid >> 5;
    int p = blockIdx.y, c = blockIdx.x, b0 = c * 32;
    uint32_t sb = smem_u32(smc);
    uint32_t wmb[3] = { sb + OFF_MB, sb + OFF_MB + 8, sb + OFF_MB + 16 };

    for (int i = tid; i < 768; i += 512) { sbhh[i] = bhh_all[p * NG + i]; sbih[i] = bih_all[p * NG + i]; }
    if (tid < 256) slw[tid] = lw_all[p * NH + tid];
    if (tid < 64) sout[tid] = 0.0f;
    float lb = lb_all[p];
    // h images from z (fp16 hi/lo split), 32 batch rows
    for (int i = tid; i < 8192; i += 512) {
        int b = i >> 8, j = i & 255;
        float z = g_z[(b0 + b) * NH + j];
        __half hi = __float2half(z);
        shi[b * 264 + j] = hi;
        slo[b * 264 + j] = __float2half(z - __half2float(hi));
    }
    // x for t=0: zeros
    for (int i = tid; i < 1024; i += 512) {
        int b = i >> 5, k = i & 31;
        sx[(0 * 32 + b) * 36 + k] = __float2half(0.0f);
    }
    if (tid == 0) { mbar_init(wmb[0], 1); mbar_init(wmb[1], 1); mbar_init(wmb[2], 1); }
    __syncthreads();
    const __half* Wf = g_Wfrag + (size_t)p * 196608;
    const __half* WihF = g_WihFrag + (size_t)p * 24576;
    if (tid == 0) {   // prime 3 slots with chunks 0,1,2 (all Whh slices)
        mbar_expect(wmb[0], SLOT_B); bulk_cp(sb, Wf, SLOT_B, wmb[0]);
        mbar_expect(wmb[1], SLOT_B); bulk_cp(sb + SLOT_B, Wf + 24576, SLOT_B, wmb[1]);
        mbar_expect(wmb[2], SLOT_B); bulk_cp(sb + 2 * SLOT_B, Wf + 49152, SLOT_B, wmb[2]);
    }
    int wph[3] = {0, 0, 0};
    int gsl = 0;
    const int NCH = TDEC * 9;            // per step: 8 Whh slices + 1 Wih chunk
    int tr0 = lane >> 2, cb0 = (lane & 3) << 1;

    for (int t = 0; t < TDEC; t++) {
        float acc[3][4][4], agi[4][4];
#pragma unroll
        for (int g = 0; g < 3; g++)
#pragma unroll
            for (int nt = 0; nt < 4; nt++)
#pragma unroll
                for (int q = 0; q < 4; q++) acc[g][nt][q] = 0.0f;
#pragma unroll
        for (int nt = 0; nt < 4; nt++)
#pragma unroll
            for (int q = 0; q < 4; q++) agi[nt][q] = 0.0f;

        const __half* sxt = sx + (t & 1) * 32 * 36;

        for (int ch = 0; ch < 9; ch++) {
            int slot = gsl % 3;
            mbar_wait(wmb[slot], wph[slot]); wph[slot] ^= 1;
            const __half* slab = (const __half*)(smc + slot * SLOT_B);
            if (ch < 8) {
                // Whh slice: 2 ktl x 3 gates x 4 n-tiles x 2 passes (hhi, hlo)
#pragma unroll
                for (int ktl = 0; ktl < 2; ktl++) {
                    int k0 = ch * 32 + ktl * 16 + cb0;
                    uint32_t bh[4][2], bl[4][2];
#pragma unroll
                    for (int nt = 0; nt < 4; nt++) {
                        int n = nt * 8 + tr0;
                        bh[nt][0] = *reinterpret_cast<const uint32_t*>(shi + n * 264 + k0);
                        bh[nt][1] = *reinterpret_cast<const uint32_t*>(shi + n * 264 + k0 + 8);
                        bl[nt][0] = *reinterpret_cast<const uint32_t*>(slo + n * 264 + k0);
                        bl[nt][1] = *reinterpret_cast<const uint32_t*>(slo + n * 264 + k0 + 8);
                    }
#pragma unroll
                    for (int g = 0; g < 3; g++) {
                        int mt = g * 16 + w;
                        uint4 a = *reinterpret_cast<const uint4*>(slab + ((mt * 2 + ktl) * 32 + lane) * 8);
#pragma unroll
                        for (int nt = 0; nt < 4; nt++) {
                            hmma(acc[g][nt], a, bh[nt][0], bh[nt][1]);
                            hmma(acc[g][nt], a, bl[nt][0], bl[nt][1]);
                        }
                    }
                }
            } else {
                // Wih chunk: K=32 -> 2 k-tiles, B = dec_in[t]; r,z -> acc, n -> agi
#pragma unroll
                for (int ktl = 0; ktl < 2; ktl++) {
                    int k0 = ktl * 16 + cb0;
                    uint32_t bx[4][2];
#pragma unroll
                    for (int nt = 0; nt < 4; nt++) {
                        int n = nt * 8 + tr0;
                        bx[nt][0] = *reinterpret_cast<const uint32_t*>(sxt + n * 36 + k0);
                        bx[nt][1] = *reinterpret_cast<const uint32_t*>(sxt + n * 36 + k0 + 8);
                    }
#pragma unroll
                    for (int g = 0; g < 3; g++) {
                        int mt = g * 16 + w;
                        uint4 a = *reinterpret_cast<const uint4*>(slab + ((mt * 2 + ktl) * 32 + lane) * 8);
#pragma unroll
                        for (int nt = 0; nt < 4; nt++) {
                            if (g < 2) hmma(acc[g][nt], a, bx[nt][0], bx[nt][1]);
                            else       hmma(agi[nt],    a, bx[nt][0], bx[nt][1]);
                        }
                    }
                }
            }
            __syncthreads();
            if (tid == 0 && gsl + 3 < NCH) {
                int nc = (gsl + 3) % 9;
                const __half* src = (nc < 8) ? (Wf + (size_t)nc * 24576) : WihF;
                mbar_expect(wmb[slot], SLOT_B);
                bulk_cp(sb + slot * SLOT_B, src, SLOT_B, wmb[slot]);
            }
            gsl++;
        }

        // ---- epilogue: gates, h update, linear head; also prep x for t+1 ----
        float red[4][2];
#pragma unroll
        for (int nt = 0; nt < 4; nt++) { red[nt][0] = 0.0f; red[nt][1] = 0.0f; }
#pragma unroll
        for (int jj = 0; jj < 2; jj++) {
            int j = w * 16 + tr0 + jj * 8;
            float br = sbhh[j], bz = sbhh[256 + j], bn = sbhh[512 + j];
            float ir = sbih[j], iz = sbih[256 + j], in_ = sbih[512 + j];
            float lwj = slw[j];
#pragma unroll
            for (int nt = 0; nt < 4; nt++) {
#pragma unroll
                for (int cs = 0; cs < 2; cs++) {
                    int ci = jj * 2 + cs;
                    int b = nt * 8 + cb0 + cs;
                    float hold = __half2float(shi[b * 264 + j]) + __half2float(slo[b * 264 + j]);
                    float r = sigm(ir + br + acc[0][nt][ci]);
                    float z = sigm(iz + bz + acc[1][nt][ci]);
                    float n = tanhf(agi[nt][ci] + in_ + r * (bn + acc[2][nt][ci]));
                    float hv = (1.0f - z) * n + z * hold;
                    __half hh = __float2half(hv);
                    shi[b * 264 + j] = hh;
                    slo[b * 264 + j] = __float2half(hv - __half2float(hh));
                    red[nt][cs] += lwj * hv;
                }
            }
        }
#pragma unroll
        for (int nt = 0; nt < 4; nt++)
#pragma unroll
            for (int cs = 0; cs < 2; cs++) {
                float v = red[nt][cs];
                v += __shfl_xor_sync(0xffffffffu, v, 4);
                v += __shfl_xor_sync(0xffffffffu, v, 8);
                v += __shfl_xor_sync(0xffffffffu, v, 16);
                if (tr0 == 0) atomicAdd(sout + (t & 1) * 32 + nt * 8 + cb0 + cs, v);
            }
        // x for step t+1 into buffer (t+1)&1 (not read until step t+1's Wih chunk)
        if (t + 1 < TDEC) {
            for (int i = tid; i < 1024; i += 512) {
                int b = i >> 5, k = i & 31;
                sx[(((t + 1) & 1) * 32 + b) * 36 + k] =
                    __float2half(X[((b0 + b) * TSEQ + 9 + (t + 1)) * NP + k]);
            }
        }
        __syncthreads();
        if (tid < 32) {
            out[((size_t)p * NB + b0 + tid) * TDEC + t] = sout[(t & 1) * 32 + tid] + lb;
            sout[(t & 1) * 32 + tid] = 0.0f;   // reused at t+2; ordered by t+1's barriers
        }
    }
}

// ======================= launcher =======================
extern "C" void kernel_launch(void* const* d_in, const int* in_sizes, int n_in,
                              void* d_out, int out_size) {
    const float* X       = (const float*)d_in[0];
    const float* eps     = (const float*)d_in[1];
    const float* Wih_enc = (const float*)d_in[2];
    const float* Whh_enc = (const float*)d_in[3];
    const float* bih_enc = (const float*)d_in[4];
    const float* bhh_enc = (const float*)d_in[5];
    const float* mw      = (const float*)d_in[6];
    const float* mb      = (const float*)d_in[7];
    const float* sw      = (const float*)d_in[8];
    const float* sb      = (const float*)d_in[9];
    const float* Wih_dec = (const float*)d_in[10];
    const float* Whh_dec = (const float*)d_in[11];
    const float* bih_dec = (const float*)d_in[12];
    const float* bhh_dec = (const float*)d_in[13];
    const float* lw      = (const float*)d_in[14];
    const float* lbv     = (const float*)d_in[15];
    float* out = (float*)d_out;

    int smem_enc = 52740 * 4;
    cudaFuncSetAttribute(enc_kernel,     cudaFuncAttributeMaxDynamicSharedMemorySize, smem_enc);
    cudaFuncSetAttribute(dec_mma_kernel, cudaFuncAttributeMaxDynamicSharedMemorySize, DEC_SMEM);

    wprep_kernel<<<dim3(96, 32), 256>>>(Whh_dec);
    wprep_ih_kernel<<<dim3(12, 32), 256>>>(Wih_dec);
    tr_enc_kernel<<<dim3(8, 24), dim3(32, 8)>>>(Whh_enc);
    trf_kernel<<<dim3(8, 8, 2), dim3(32, 8)>>>(mw, sw);
    enc_kernel<<<16, 512, smem_enc>>>(X, Wih_enc, bih_enc, bhh_enc);
    lat_kernel<<<NB, 256>>>(eps, mb, sb, out);
    dec_mma_kernel<<<dim3(2, NP), 512, DEC_SMEM>>>(X, bih_dec, bhh_dec, lw, lbv, out);
}